// round 3
// baseline (speedup 1.0000x reference)
#include <cuda_runtime.h>
#include <math.h>

// Problem dims
#define B_SZ   8
#define SLEN   4096            // n*h tokens per batch for attention
#define DH     256
#define MDIM   1024
#define R_TOTAL (B_SZ * SLEN)  // 32768 rows total
#define SCALE  0.0625f         // 256^-0.5

// Scratch (device globals: allocation-free rule)
__device__ float g_xn [R_TOTAL * DH];
__device__ float g_q  [R_TOTAL * DH];
__device__ float g_k  [R_TOTAL * DH];
__device__ float g_v  [R_TOTAL * DH];
__device__ float g_hid[R_TOTAL * MDIM];

// ---------- packed f32x2 helpers (2x FFMA throughput on sm_103a) ----------
typedef unsigned long long ull;
__device__ __forceinline__ ull pack2(float lo, float hi) {
    ull r; asm("mov.b64 %0, {%1, %2};" : "=l"(r) : "f"(lo), "f"(hi)); return r;
}
__device__ __forceinline__ ull fma2(ull a, ull b, ull c) {
    ull d; asm("fma.rn.f32x2 %0, %1, %2, %3;" : "=l"(d) : "l"(a), "l"(b), "l"(c)); return d;
}
__device__ __forceinline__ ull mul2(ull a, ull b) {
    ull d; asm("mul.rn.f32x2 %0, %1, %2;" : "=l"(d) : "l"(a), "l"(b)); return d;
}
__device__ __forceinline__ float2 unpk(ull v) {
    float2 f; asm("mov.b64 {%0, %1}, %2;" : "=f"(f.x), "=f"(f.y) : "l"(v)); return f;
}

// ---------- LayerNorm: one warp per row of 256, writes g_xn ----------
__global__ __launch_bounds__(128) void ln_kernel(const float* __restrict__ x,
                                                 const float* __restrict__ gma,
                                                 const float* __restrict__ bta) {
    const int w = threadIdx.x >> 5;
    const int lane = threadIdx.x & 31;
    const long row = (long)blockIdx.x * 4 + w;
    const float4* xr = (const float4*)(x + row * DH);
    float4 a = xr[lane];
    float4 b = xr[lane + 32];
    float s  = a.x + a.y + a.z + a.w + b.x + b.y + b.z + b.w;
    float ss = a.x*a.x + a.y*a.y + a.z*a.z + a.w*a.w
             + b.x*b.x + b.y*b.y + b.z*b.z + b.w*b.w;
#pragma unroll
    for (int off = 16; off; off >>= 1) {
        s  += __shfl_xor_sync(0xffffffffu, s,  off);
        ss += __shfl_xor_sync(0xffffffffu, ss, off);
    }
    const float mu  = s * (1.0f / 256.0f);
    const float var = ss * (1.0f / 256.0f) - mu * mu;
    const float rs  = rsqrtf(var + 1e-5f);
    const float4* g4 = (const float4*)gma;
    const float4* e4 = (const float4*)bta;
    float4 ga = g4[lane], gb = g4[lane + 32];
    float4 ba = e4[lane], bb = e4[lane + 32];
    float4* yr = (float4*)(g_xn + row * DH);
    float4 o;
    o.x = (a.x - mu) * rs * ga.x + ba.x;
    o.y = (a.y - mu) * rs * ga.y + ba.y;
    o.z = (a.z - mu) * rs * ga.z + ba.z;
    o.w = (a.w - mu) * rs * ga.w + ba.w;
    yr[lane] = o;
    o.x = (b.x - mu) * rs * gb.x + bb.x;
    o.y = (b.y - mu) * rs * gb.y + bb.y;
    o.z = (b.z - mu) * rs * gb.z + bb.z;
    o.w = (b.w - mu) * rs * gb.w + bb.w;
    yr[lane + 32] = o;
}

// ---------- Tiled GEMM: C[R x N] = A[R x K] * W[N x K]^T ----------
// BM=BN=64, BK=16, 256 threads, 4x4 outputs/thread, f32x2 inner loop.
// EPI: 0 = QKV scatter (e -> comp e%3, col e/3) into g_q/g_k/g_v
//      1 = +b1, SiLU, store g_hid
//      2 = +b2, += out (residual), store out
template<int KDIM, int EPI>
__global__ __launch_bounds__(256) void gemm_kernel(const float* __restrict__ W,
                                                   const float* __restrict__ bias,
                                                   float* __restrict__ out) {
    __shared__ float As[16 * 64];  // [k][m]
    __shared__ float Ws[16 * 64];  // [k][n]
    const float* A = (EPI == 2) ? (const float*)g_hid : (const float*)g_xn;
    const int row0 = blockIdx.y * 64;
    const int col0 = blockIdx.x * 64;
    const int t  = threadIdx.x;
    const int tx = t & 15, ty = t >> 4;
    const int i0 = ty * 4, j0 = tx * 4;
    const int lm = t >> 2, lk = (t & 3) * 4;
    const float* Ag = A + (long)(row0 + lm) * KDIM + lk;
    const float* Wg = W + (long)(col0 + lm) * KDIM + lk;

    ull acc[4][2];
#pragma unroll
    for (int r = 0; r < 4; r++) { acc[r][0] = 0ull; acc[r][1] = 0ull; }

    for (int kt = 0; kt < KDIM / 16; kt++) {
        __syncthreads();
        float4 av = *(const float4*)(Ag + kt * 16);
        float4 wv = *(const float4*)(Wg + kt * 16);
        As[(lk + 0) * 64 + lm] = av.x;
        As[(lk + 1) * 64 + lm] = av.y;
        As[(lk + 2) * 64 + lm] = av.z;
        As[(lk + 3) * 64 + lm] = av.w;
        Ws[(lk + 0) * 64 + lm] = wv.x;
        Ws[(lk + 1) * 64 + lm] = wv.y;
        Ws[(lk + 2) * 64 + lm] = wv.z;
        Ws[(lk + 3) * 64 + lm] = wv.w;
        __syncthreads();
#pragma unroll
        for (int kk = 0; kk < 16; kk++) {
            float4 a4 = *(const float4*)&As[kk * 64 + i0];
            float4 w4 = *(const float4*)&Ws[kk * 64 + j0];
            ull w0 = pack2(w4.x, w4.y), w1 = pack2(w4.z, w4.w);
            ull ap;
            ap = pack2(a4.x, a4.x); acc[0][0] = fma2(ap, w0, acc[0][0]); acc[0][1] = fma2(ap, w1, acc[0][1]);
            ap = pack2(a4.y, a4.y); acc[1][0] = fma2(ap, w0, acc[1][0]); acc[1][1] = fma2(ap, w1, acc[1][1]);
            ap = pack2(a4.z, a4.z); acc[2][0] = fma2(ap, w0, acc[2][0]); acc[2][1] = fma2(ap, w1, acc[2][1]);
            ap = pack2(a4.w, a4.w); acc[3][0] = fma2(ap, w0, acc[3][0]); acc[3][1] = fma2(ap, w1, acc[3][1]);
        }
    }

    float c[4][4];
#pragma unroll
    for (int r = 0; r < 4; r++) {
        float2 c0 = unpk(acc[r][0]), c1 = unpk(acc[r][1]);
        c[r][0] = c0.x; c[r][1] = c0.y; c[r][2] = c1.x; c[r][3] = c1.y;
    }

#pragma unroll
    for (int r = 0; r < 4; r++) {
        const long row = row0 + i0 + r;
#pragma unroll
        for (int cc = 0; cc < 4; cc++) {
            const int e = col0 + j0 + cc;
            if (EPI == 0) {
                const int comp = e % 3;
                const int jc = e / 3;
                float* dst = (comp == 0) ? g_q : ((comp == 1) ? g_k : g_v);
                dst[row * DH + jc] = c[r][cc];
            } else if (EPI == 1) {
                const float z = c[r][cc] + bias[e];
                g_hid[row * MDIM + e] = z / (1.0f + __expf(-z));
            } else {
                const long o = row * DH + e;
                out[o] = out[o] + c[r][cc] + bias[e];
            }
        }
    }
}

// ---------- Flash attention, fp32 f32x2, 64-row q tile, 64-row kv tiles ----------
// smem: Qs[256][64] k-major, Ks[256][64] k-major, Vs[64][256], Ps[64][68]
#define FLASH_SMEM ((16384 * 3 + 64 * 68) * 4)   // 214016 bytes

__global__ __launch_bounds__(256, 1) void flash_kernel(const float* __restrict__ x,
                                                       float* __restrict__ out) {
    extern __shared__ float sm[];
    float* Qs = sm;
    float* Ks = sm + 16384;
    float* Vs = sm + 32768;
    float* Ps = sm + 49152;
    const int b  = blockIdx.y;
    const int q0 = blockIdx.x * 64;
    const long base = (long)b * SLEN * DH;
    const int t  = threadIdx.x;
    const int tx = t & 15, ty = t >> 4;
    const int i0 = ty * 4, j0 = tx * 4;

    // Load Q tile transposed to k-major
    {
        const float* qg = g_q + base + (long)q0 * DH;
#pragma unroll
        for (int it = 0; it < 16; it++) {
            int idx = t + it * 256;
            int col = idx & 63, k4 = idx >> 6;
            float4 v = *(const float4*)(qg + col * DH + k4 * 4);
            Qs[(k4 * 4 + 0) * 64 + col] = v.x;
            Qs[(k4 * 4 + 1) * 64 + col] = v.y;
            Qs[(k4 * 4 + 2) * 64 + col] = v.z;
            Qs[(k4 * 4 + 3) * 64 + col] = v.w;
        }
    }

    float m_[4] = {-1e30f, -1e30f, -1e30f, -1e30f};
    float l_[4] = {0.f, 0.f, 0.f, 0.f};
    ull accO[4][8];
#pragma unroll
    for (int r = 0; r < 4; r++)
#pragma unroll
        for (int cq = 0; cq < 8; cq++) accO[r][cq] = 0ull;

    for (int kt = 0; kt < 64; kt++) {
        __syncthreads();   // previous tile fully consumed before overwriting K/V/P
        const float* kg = g_k + base + (long)kt * 64 * DH;
        const float* vg = g_v + base + (long)kt * 64 * DH;
#pragma unroll
        for (int it = 0; it < 16; it++) {
            int idx = t + it * 256;
            int col = idx & 63, k4 = idx >> 6;
            float4 kv = *(const float4*)(kg + col * DH + k4 * 4);
            Ks[(k4 * 4 + 0) * 64 + col] = kv.x;
            Ks[(k4 * 4 + 1) * 64 + col] = kv.y;
            Ks[(k4 * 4 + 2) * 64 + col] = kv.z;
            Ks[(k4 * 4 + 3) * 64 + col] = kv.w;
            // V row-major copy (k4 = v-row, col = col4)
            *(float4*)&Vs[k4 * 256 + col * 4] = *(const float4*)(vg + k4 * DH + col * 4);
        }
        __syncthreads();

        // S = Q K^T  (4 rows x 4 cols per thread, f32x2 over col pairs)
        ull accS[4][2];
#pragma unroll
        for (int r = 0; r < 4; r++) { accS[r][0] = 0ull; accS[r][1] = 0ull; }
#pragma unroll 4
        for (int kk = 0; kk < 256; kk++) {
            float4 q4  = *(const float4*)&Qs[kk * 64 + i0];
            float4 k4v = *(const float4*)&Ks[kk * 64 + j0];
            ull w0 = pack2(k4v.x, k4v.y), w1 = pack2(k4v.z, k4v.w);
            ull ap;
            ap = pack2(q4.x, q4.x); accS[0][0] = fma2(ap, w0, accS[0][0]); accS[0][1] = fma2(ap, w1, accS[0][1]);
            ap = pack2(q4.y, q4.y); accS[1][0] = fma2(ap, w0, accS[1][0]); accS[1][1] = fma2(ap, w1, accS[1][1]);
            ap = pack2(q4.z, q4.z); accS[2][0] = fma2(ap, w0, accS[2][0]); accS[2][1] = fma2(ap, w1, accS[2][1]);
            ap = pack2(q4.w, q4.w); accS[3][0] = fma2(ap, w0, accS[3][0]); accS[3][1] = fma2(ap, w1, accS[3][1]);
        }

        // Online softmax update (row stats replicated across the 16 tx lanes)
#pragma unroll
        for (int r = 0; r < 4; r++) {
            float2 s0 = unpk(accS[r][0]), s1 = unpk(accS[r][1]);
            float p0 = s0.x * SCALE, p1 = s0.y * SCALE;
            float p2 = s1.x * SCALE, p3 = s1.y * SCALE;
            float mx = fmaxf(fmaxf(p0, p1), fmaxf(p2, p3));
#pragma unroll
            for (int off = 8; off; off >>= 1)
                mx = fmaxf(mx, __shfl_xor_sync(0xffffffffu, mx, off, 16));
            const float mn = fmaxf(m_[r], mx);
            const float al = __expf(m_[r] - mn);
            m_[r] = mn;
            p0 = __expf(p0 - mn); p1 = __expf(p1 - mn);
            p2 = __expf(p2 - mn); p3 = __expf(p3 - mn);
            float sum = p0 + p1 + p2 + p3;
#pragma unroll
            for (int off = 8; off; off >>= 1)
                sum += __shfl_xor_sync(0xffffffffu, sum, off, 16);
            l_[r] = l_[r] * al + sum;
            const ull ap2 = pack2(al, al);
#pragma unroll
            for (int cq = 0; cq < 8; cq++) accO[r][cq] = mul2(ap2, accO[r][cq]);
            Ps[(j0 + 0) * 68 + i0 + r] = p0;
            Ps[(j0 + 1) * 68 + i0 + r] = p1;
            Ps[(j0 + 2) * 68 + i0 + r] = p2;
            Ps[(j0 + 3) * 68 + i0 + r] = p3;
        }
        __syncthreads();

        // O += P V  (4 rows x 16 d-cols per thread as 4 chunks of 4)
#pragma unroll 2
        for (int j = 0; j < 64; j++) {
            float4 p4 = *(const float4*)&Ps[j * 68 + i0];
            ull pp0 = pack2(p4.x, p4.x), pp1 = pack2(p4.y, p4.y);
            ull pp2 = pack2(p4.z, p4.z), pp3 = pack2(p4.w, p4.w);
#pragma unroll
            for (int ch = 0; ch < 4; ch++) {
                float4 v4 = *(const float4*)&Vs[j * 256 + j0 + ch * 64];
                ull v0 = pack2(v4.x, v4.y), v1 = pack2(v4.z, v4.w);
                accO[0][2*ch]   = fma2(pp0, v0, accO[0][2*ch]);
                accO[0][2*ch+1] = fma2(pp0, v1, accO[0][2*ch+1]);
                accO[1][2*ch]   = fma2(pp1, v0, accO[1][2*ch]);
                accO[1][2*ch+1] = fma2(pp1, v1, accO[1][2*ch+1]);
                accO[2][2*ch]   = fma2(pp2, v0, accO[2][2*ch]);
                accO[2][2*ch+1] = fma2(pp2, v1, accO[2][2*ch+1]);
                accO[3][2*ch]   = fma2(pp3, v0, accO[3][2*ch]);
                accO[3][2*ch+1] = fma2(pp3, v1, accO[3][2*ch+1]);
            }
        }
    }

    // Epilogue: out = x + O / l  (residual fused here)
#pragma unroll
    for (int r = 0; r < 4; r++) {
        const long row = (long)b * SLEN + q0 + i0 + r;
        const float inv = 1.0f / l_[r];
#pragma unroll
        for (int ch = 0; ch < 4; ch++) {
            float2 o0 = unpk(accO[r][2*ch]), o1 = unpk(accO[r][2*ch+1]);
            const long off = row * DH + j0 + ch * 64;
            float4 xv = *(const float4*)(x + off);
            float4 res;
            res.x = xv.x + o0.x * inv;
            res.y = xv.y + o0.y * inv;
            res.z = xv.z + o1.x * inv;
            res.w = xv.w + o1.y * inv;
            *(float4*)(out + off) = res;
        }
    }
}

extern "C" void kernel_launch(void* const* d_in, const int* in_sizes, int n_in,
                              void* d_out, int out_size) {
    const float* x      = (const float*)d_in[0];
    const float* w_qkv  = (const float*)d_in[1];
    const float* gamma1 = (const float*)d_in[2];
    const float* beta1  = (const float*)d_in[3];
    const float* gamma2 = (const float*)d_in[4];
    const float* beta2  = (const float*)d_in[5];
    const float* w1     = (const float*)d_in[6];
    const float* b1     = (const float*)d_in[7];
    const float* w2     = (const float*)d_in[8];
    const float* b2     = (const float*)d_in[9];
    float* out = (float*)d_out;

    cudaFuncSetAttribute(flash_kernel, cudaFuncAttributeMaxDynamicSharedMemorySize, FLASH_SMEM);

    // 1) xn = LN1(x)
    ln_kernel<<<R_TOTAL / 4, 128>>>(x, gamma1, beta1);
    // 2) q,k,v = xn @ w_qkv^T with (d,3) interleave scatter
    gemm_kernel<256, 0><<<dim3(768 / 64, R_TOTAL / 64), 256>>>(w_qkv, nullptr, nullptr);
    // 3) out = x + attention(q,k,v)
    flash_kernel<<<dim3(SLEN / 64, B_SZ), 256, FLASH_SMEM>>>(x, out);
    // 4) xn = LN2(out)
    ln_kernel<<<R_TOTAL / 4, 128>>>(out, gamma2, beta2);
    // 5) hid = silu(xn @ w1^T + b1)
    gemm_kernel<256, 1><<<dim3(MDIM / 64, R_TOTAL / 64), 256>>>(w1, b1, nullptr);
    // 6) out += hid @ w2^T + b2
    gemm_kernel<1024, 2><<<dim3(DH / 64, R_TOTAL / 64), 256>>>(w2, b2, out);
}

// round 4
// speedup vs baseline: 2.9689x; 2.9689x over previous
#include <cuda_runtime.h>
#include <math.h>

// Problem dims
#define B_SZ   8
#define SLEN   4096            // n*h tokens per batch for attention
#define DH     256
#define MDIM   1024
#define R_TOTAL (B_SZ * SLEN)  // 32768 rows total
#define SCALE  0.0625f         // 256^-0.5

// Scratch (device globals: allocation-free rule)
__device__ float g_xn [R_TOTAL * DH];
__device__ float g_q  [R_TOTAL * DH];   // tf32-rounded
__device__ float g_k  [R_TOTAL * DH];   // tf32-rounded
__device__ float g_v  [R_TOTAL * DH];   // tf32-rounded
__device__ float g_hid[R_TOTAL * MDIM];

// ---------------- tf32 mma helpers ----------------
__device__ __forceinline__ unsigned cvt_tf32(float f) {
    unsigned r; asm("cvt.rna.tf32.f32 %0, %1;" : "=r"(r) : "f"(f)); return r;
}
__device__ __forceinline__ float cvt_tf32f(float f) {
    return __uint_as_float(cvt_tf32(f));
}
__device__ __forceinline__ unsigned asu(float f) { return __float_as_uint(f); }

__device__ __forceinline__ void mma_tf32(float c[4],
                                         unsigned a0, unsigned a1, unsigned a2, unsigned a3,
                                         unsigned b0, unsigned b1) {
    asm volatile(
        "mma.sync.aligned.m16n8k8.row.col.f32.tf32.tf32.f32 "
        "{%0,%1,%2,%3}, {%4,%5,%6,%7}, {%8,%9}, {%0,%1,%2,%3};"
        : "+f"(c[0]), "+f"(c[1]), "+f"(c[2]), "+f"(c[3])
        : "r"(a0), "r"(a1), "r"(a2), "r"(a3), "r"(b0), "r"(b1));
}

// ---------- LayerNorm: one warp per row of 256, writes g_xn ----------
__global__ __launch_bounds__(128) void ln_kernel(const float* __restrict__ x,
                                                 const float* __restrict__ gma,
                                                 const float* __restrict__ bta) {
    const int w = threadIdx.x >> 5;
    const int lane = threadIdx.x & 31;
    const long row = (long)blockIdx.x * 4 + w;
    const float4* xr = (const float4*)(x + row * DH);
    float4 a = xr[lane];
    float4 b = xr[lane + 32];
    float s  = a.x + a.y + a.z + a.w + b.x + b.y + b.z + b.w;
    float ss = a.x*a.x + a.y*a.y + a.z*a.z + a.w*a.w
             + b.x*b.x + b.y*b.y + b.z*b.z + b.w*b.w;
#pragma unroll
    for (int off = 16; off; off >>= 1) {
        s  += __shfl_xor_sync(0xffffffffu, s,  off);
        ss += __shfl_xor_sync(0xffffffffu, ss, off);
    }
    const float mu  = s * (1.0f / 256.0f);
    const float var = ss * (1.0f / 256.0f) - mu * mu;
    const float rs  = rsqrtf(var + 1e-5f);
    const float4* g4 = (const float4*)gma;
    const float4* e4 = (const float4*)bta;
    float4 ga = g4[lane], gb = g4[lane + 32];
    float4 ba = e4[lane], bb = e4[lane + 32];
    float4* yr = (float4*)(g_xn + row * DH);
    float4 o;
    o.x = (a.x - mu) * rs * ga.x + ba.x;
    o.y = (a.y - mu) * rs * ga.y + ba.y;
    o.z = (a.z - mu) * rs * ga.z + ba.z;
    o.w = (a.w - mu) * rs * ga.w + ba.w;
    yr[lane] = o;
    o.x = (b.x - mu) * rs * gb.x + bb.x;
    o.y = (b.y - mu) * rs * gb.y + bb.y;
    o.z = (b.z - mu) * rs * gb.z + bb.z;
    o.w = (b.w - mu) * rs * gb.w + bb.w;
    yr[lane + 32] = o;
}

// ---------- TF32 MMA GEMM: C[R x N] = A[R x K] * W[N x K]^T ----------
// BM=128, BN=64, BK=32; 256 threads = 8 warps, warp w owns rows [16w,16w+16), all 64 cols.
// EPI: 0 = QKV scatter (e -> comp e%3, col e/3) into g_q/g_k/g_v (tf32-rounded)
//      1 = +b1, SiLU, store g_hid
//      2 = +b2, += out (residual), store out
#define GA_STRIDE 36   // 36 % 32 == 4 -> conflict-free A/B fragment LDS
template<int KDIM, int EPI>
__global__ __launch_bounds__(256) void gemm_kernel(const float* __restrict__ W,
                                                   const float* __restrict__ bias,
                                                   float* __restrict__ out) {
    __shared__ float As[128 * GA_STRIDE];
    __shared__ float Bs[64 * GA_STRIDE];
    const float* A = (EPI == 2) ? (const float*)g_hid : (const float*)g_xn;
    const int row0 = blockIdx.y * 128;
    const int col0 = blockIdx.x * 64;
    const int t  = threadIdx.x;
    const int w  = t >> 5;
    const int lane = t & 31;
    const int qr = lane >> 2;   // group id (row within fragment)
    const int ql = lane & 3;    // thread in group (k within fragment)

    float Cacc[8][4];
#pragma unroll
    for (int nt = 0; nt < 8; nt++)
#pragma unroll
        for (int j = 0; j < 4; j++) Cacc[nt][j] = 0.f;

    for (int kt = 0; kt < KDIM / 32; kt++) {
        const int k0 = kt * 32;
        __syncthreads();
        // stage A (128x32) — 4 float4 per thread, tf32 convert
#pragma unroll
        for (int i = 0; i < 4; i++) {
            int idx = t + i * 256;
            int row = idx >> 3, c4 = (idx & 7) * 4;
            float4 v = *(const float4*)(A + (long)(row0 + row) * KDIM + k0 + c4);
            float4 cv = make_float4(cvt_tf32f(v.x), cvt_tf32f(v.y), cvt_tf32f(v.z), cvt_tf32f(v.w));
            *(float4*)&As[row * GA_STRIDE + c4] = cv;
        }
        // stage W (64x32) — 2 float4 per thread
#pragma unroll
        for (int i = 0; i < 2; i++) {
            int idx = t + i * 256;
            int row = idx >> 3, c4 = (idx & 7) * 4;
            float4 v = *(const float4*)(W + (long)(col0 + row) * KDIM + k0 + c4);
            float4 cv = make_float4(cvt_tf32f(v.x), cvt_tf32f(v.y), cvt_tf32f(v.z), cvt_tf32f(v.w));
            *(float4*)&Bs[row * GA_STRIDE + c4] = cv;
        }
        __syncthreads();
#pragma unroll
        for (int s = 0; s < 4; s++) {
            const int kk = s * 8 + ql;
            unsigned a0 = asu(As[(w * 16 + qr    ) * GA_STRIDE + kk    ]);
            unsigned a1 = asu(As[(w * 16 + qr + 8) * GA_STRIDE + kk    ]);
            unsigned a2 = asu(As[(w * 16 + qr    ) * GA_STRIDE + kk + 4]);
            unsigned a3 = asu(As[(w * 16 + qr + 8) * GA_STRIDE + kk + 4]);
#pragma unroll
            for (int nt = 0; nt < 8; nt++) {
                unsigned b0 = asu(Bs[(nt * 8 + qr) * GA_STRIDE + kk    ]);
                unsigned b1 = asu(Bs[(nt * 8 + qr) * GA_STRIDE + kk + 4]);
                mma_tf32(Cacc[nt], a0, a1, a2, a3, b0, b1);
            }
        }
    }

    // epilogue: thread owns rows (row0+16w+qr, +8), cols col0 + nt*8 + 2*ql + {0,1}
    const long r_lo = row0 + w * 16 + qr;
    const long r_hi = r_lo + 8;
#pragma unroll
    for (int nt = 0; nt < 8; nt++) {
#pragma unroll
        for (int j = 0; j < 4; j++) {
            const long row = (j < 2) ? r_lo : r_hi;
            const int e = col0 + nt * 8 + 2 * ql + (j & 1);
            const float val = Cacc[nt][j];
            if (EPI == 0) {
                const int comp = e % 3;
                const int jc = e / 3;
                float* dst = (comp == 0) ? g_q : ((comp == 1) ? g_k : g_v);
                dst[row * DH + jc] = cvt_tf32f(val);
            } else if (EPI == 1) {
                const float z = val + bias[e];
                g_hid[row * MDIM + e] = z / (1.0f + __expf(-z));
            } else {
                const long o = row * DH + e;
                out[o] = out[o] + val + bias[e];
            }
        }
    }
}

// ---------- Flash attention with TF32 MMA ----------
// 64-row q tile, 64-row kv tiles, 256 threads = 8 warps.
// S warp layout: rows 16*(w&3), cols 32*(w>>2).
// O warp layout: rows 16*(w&3), d-half 128*(w>>2), 16 n-tiles of 8.
#define QS_STR 260   // 260 % 32 == 4: conflict-free A/B-row fragment loads
#define VS_STR 264   // 264 % 32 == 8: conflict-free B(k-major) fragment loads
#define PS_STR 68    //  68 % 32 == 4
// floats: Q 64*260 + K 64*260 + V 64*264 + P 64*68 + red 256
#define FLASH_FLOATS (64*QS_STR*2 + 64*VS_STR + 64*PS_STR + 256)
#define FLASH_SMEM   (FLASH_FLOATS * 4)

__global__ __launch_bounds__(256, 1) void flash_kernel(const float* __restrict__ x,
                                                       float* __restrict__ out) {
    extern __shared__ float sm[];
    float* Qs   = sm;
    float* Ks   = Qs + 64 * QS_STR;
    float* Vs   = Ks + 64 * QS_STR;
    float* Ps   = Vs + 64 * VS_STR;
    float* redm = Ps + 64 * PS_STR;   // [2][64]
    float* reds = redm + 128;         // [2][64]

    const int b  = blockIdx.y;
    const int q0 = blockIdx.x * 64;
    const long base = (long)b * SLEN * DH;
    const int t  = threadIdx.x;
    const int w  = t >> 5;
    const int lane = t & 31;
    const int qr = lane >> 2;
    const int ql = lane & 3;
    const int rs = (w & 3) * 16;      // row strip
    const int cs = (w >> 2) * 32;     // S col half
    const int d0 = (w >> 2) * 128;    // O d half

    // stage Q tile (already tf32-rounded in g_q)
    {
        const float* qg = g_q + base + (long)q0 * DH;
#pragma unroll
        for (int i = 0; i < 16; i++) {
            int idx = t + i * 256;
            int row = idx >> 6, c4 = (idx & 63) * 4;
            *(float4*)&Qs[row * QS_STR + c4] = *(const float4*)(qg + row * DH + c4);
        }
    }

    float m_lo = -1e30f, m_hi = -1e30f, l_lo = 0.f, l_hi = 0.f;
    float Oacc[16][4];
#pragma unroll
    for (int nt = 0; nt < 16; nt++)
#pragma unroll
        for (int j = 0; j < 4; j++) Oacc[nt][j] = 0.f;

    for (int kt = 0; kt < 64; kt++) {
        __syncthreads();   // prev tile fully consumed
        const float* kg = g_k + base + (long)kt * 64 * DH;
        const float* vg = g_v + base + (long)kt * 64 * DH;
#pragma unroll
        for (int i = 0; i < 16; i++) {
            int idx = t + i * 256;
            int row = idx >> 6, c4 = (idx & 63) * 4;
            *(float4*)&Ks[row * QS_STR + c4] = *(const float4*)(kg + row * DH + c4);
            *(float4*)&Vs[row * VS_STR + c4] = *(const float4*)(vg + row * DH + c4);
        }
        __syncthreads();

        // ---- S = Q K^T (this warp: 16 x 32) ----
        float Sacc[4][4];
#pragma unroll
        for (int nt = 0; nt < 4; nt++)
#pragma unroll
            for (int j = 0; j < 4; j++) Sacc[nt][j] = 0.f;
#pragma unroll 8
        for (int s = 0; s < 32; s++) {
            const int kk = s * 8 + ql;
            unsigned a0 = asu(Qs[(rs + qr    ) * QS_STR + kk    ]);
            unsigned a1 = asu(Qs[(rs + qr + 8) * QS_STR + kk    ]);
            unsigned a2 = asu(Qs[(rs + qr    ) * QS_STR + kk + 4]);
            unsigned a3 = asu(Qs[(rs + qr + 8) * QS_STR + kk + 4]);
#pragma unroll
            for (int nt = 0; nt < 4; nt++) {
                unsigned b0 = asu(Ks[(cs + nt * 8 + qr) * QS_STR + kk    ]);
                unsigned b1 = asu(Ks[(cs + nt * 8 + qr) * QS_STR + kk + 4]);
                mma_tf32(Sacc[nt], a0, a1, a2, a3, b0, b1);
            }
        }
        // scale
#pragma unroll
        for (int nt = 0; nt < 4; nt++)
#pragma unroll
            for (int j = 0; j < 4; j++) Sacc[nt][j] *= SCALE;

        // ---- row max (quad reduce, then cross-warp via smem) ----
        float mx_lo = -1e30f, mx_hi = -1e30f;
#pragma unroll
        for (int nt = 0; nt < 4; nt++) {
            mx_lo = fmaxf(mx_lo, fmaxf(Sacc[nt][0], Sacc[nt][1]));
            mx_hi = fmaxf(mx_hi, fmaxf(Sacc[nt][2], Sacc[nt][3]));
        }
        mx_lo = fmaxf(mx_lo, __shfl_xor_sync(0xffffffffu, mx_lo, 1));
        mx_lo = fmaxf(mx_lo, __shfl_xor_sync(0xffffffffu, mx_lo, 2));
        mx_hi = fmaxf(mx_hi, __shfl_xor_sync(0xffffffffu, mx_hi, 1));
        mx_hi = fmaxf(mx_hi, __shfl_xor_sync(0xffffffffu, mx_hi, 2));
        if (ql == 0) {
            redm[(w >> 2) * 64 + rs + qr    ] = mx_lo;
            redm[(w >> 2) * 64 + rs + qr + 8] = mx_hi;
        }
        __syncthreads();
        const float Mlo = fmaxf(redm[rs + qr    ], redm[64 + rs + qr    ]);
        const float Mhi = fmaxf(redm[rs + qr + 8], redm[64 + rs + qr + 8]);
        const float mn_lo = fmaxf(m_lo, Mlo);
        const float mn_hi = fmaxf(m_hi, Mhi);
        const float al_lo = __expf(m_lo - mn_lo);
        const float al_hi = __expf(m_hi - mn_hi);
        m_lo = mn_lo; m_hi = mn_hi;

        // ---- exp, sums, store P (tf32-rounded) ----
        float sum_lo = 0.f, sum_hi = 0.f;
#pragma unroll
        for (int nt = 0; nt < 4; nt++) {
            float p0 = __expf(Sacc[nt][0] - mn_lo);
            float p1 = __expf(Sacc[nt][1] - mn_lo);
            float p2 = __expf(Sacc[nt][2] - mn_hi);
            float p3 = __expf(Sacc[nt][3] - mn_hi);
            sum_lo += p0 + p1; sum_hi += p2 + p3;
            const int col = cs + nt * 8 + 2 * ql;
            Ps[(rs + qr    ) * PS_STR + col    ] = cvt_tf32f(p0);
            Ps[(rs + qr    ) * PS_STR + col + 1] = cvt_tf32f(p1);
            Ps[(rs + qr + 8) * PS_STR + col    ] = cvt_tf32f(p2);
            Ps[(rs + qr + 8) * PS_STR + col + 1] = cvt_tf32f(p3);
        }
        sum_lo += __shfl_xor_sync(0xffffffffu, sum_lo, 1);
        sum_lo += __shfl_xor_sync(0xffffffffu, sum_lo, 2);
        sum_hi += __shfl_xor_sync(0xffffffffu, sum_hi, 1);
        sum_hi += __shfl_xor_sync(0xffffffffu, sum_hi, 2);
        if (ql == 0) {
            reds[(w >> 2) * 64 + rs + qr    ] = sum_lo;
            reds[(w >> 2) * 64 + rs + qr + 8] = sum_hi;
        }
        // rescale O accumulators
#pragma unroll
        for (int nt = 0; nt < 16; nt++) {
            Oacc[nt][0] *= al_lo; Oacc[nt][1] *= al_lo;
            Oacc[nt][2] *= al_hi; Oacc[nt][3] *= al_hi;
        }
        __syncthreads();   // Ps + reds ready
        l_lo = l_lo * al_lo + reds[rs + qr    ] + reds[64 + rs + qr    ];
        l_hi = l_hi * al_hi + reds[rs + qr + 8] + reds[64 + rs + qr + 8];

        // ---- O += P V (this warp: 16 rows x 128 d-cols) ----
#pragma unroll
        for (int j8 = 0; j8 < 8; j8++) {
            const int kk = j8 * 8 + ql;
            unsigned a0 = asu(Ps[(rs + qr    ) * PS_STR + kk    ]);
            unsigned a1 = asu(Ps[(rs + qr + 8) * PS_STR + kk    ]);
            unsigned a2 = asu(Ps[(rs + qr    ) * PS_STR + kk + 4]);
            unsigned a3 = asu(Ps[(rs + qr + 8) * PS_STR + kk + 4]);
#pragma unroll
            for (int nt = 0; nt < 16; nt++) {
                unsigned b0 = asu(Vs[(kk    ) * VS_STR + d0 + nt * 8 + qr]);
                unsigned b1 = asu(Vs[(kk + 4) * VS_STR + d0 + nt * 8 + qr]);
                mma_tf32(Oacc[nt], a0, a1, a2, a3, b0, b1);
            }
        }
    }

    // epilogue: out = x + O / l
    const float inv_lo = 1.0f / l_lo;
    const float inv_hi = 1.0f / l_hi;
    const long r_lo = (long)b * SLEN + q0 + rs + qr;
    const long r_hi = r_lo + 8;
#pragma unroll
    for (int nt = 0; nt < 16; nt++) {
        const int col = d0 + nt * 8 + 2 * ql;
        {
            const long off = r_lo * DH + col;
            float2 xv = *(const float2*)(x + off);
            float2 res = make_float2(xv.x + Oacc[nt][0] * inv_lo,
                                     xv.y + Oacc[nt][1] * inv_lo);
            *(float2*)(out + off) = res;
        }
        {
            const long off = r_hi * DH + col;
            float2 xv = *(const float2*)(x + off);
            float2 res = make_float2(xv.x + Oacc[nt][2] * inv_hi,
                                     xv.y + Oacc[nt][3] * inv_hi);
            *(float2*)(out + off) = res;
        }
    }
}

extern "C" void kernel_launch(void* const* d_in, const int* in_sizes, int n_in,
                              void* d_out, int out_size) {
    const float* x      = (const float*)d_in[0];
    const float* w_qkv  = (const float*)d_in[1];
    const float* gamma1 = (const float*)d_in[2];
    const float* beta1  = (const float*)d_in[3];
    const float* gamma2 = (const float*)d_in[4];
    const float* beta2  = (const float*)d_in[5];
    const float* w1     = (const float*)d_in[6];
    const float* b1     = (const float*)d_in[7];
    const float* w2     = (const float*)d_in[8];
    const float* b2     = (const float*)d_in[9];
    float* out = (float*)d_out;

    cudaFuncSetAttribute(flash_kernel, cudaFuncAttributeMaxDynamicSharedMemorySize, FLASH_SMEM);

    // 1) xn = LN1(x)
    ln_kernel<<<R_TOTAL / 4, 128>>>(x, gamma1, beta1);
    // 2) q,k,v = xn @ w_qkv^T with (d,3) interleave scatter (tf32-rounded outputs)
    gemm_kernel<256, 0><<<dim3(768 / 64, R_TOTAL / 128), 256>>>(w_qkv, nullptr, nullptr);
    // 3) out = x + attention(q,k,v)
    flash_kernel<<<dim3(SLEN / 64, B_SZ), 256, FLASH_SMEM>>>(x, out);
    // 4) xn = LN2(out)
    ln_kernel<<<R_TOTAL / 4, 128>>>(out, gamma2, beta2);
    // 5) hid = silu(xn @ w1^T + b1)
    gemm_kernel<256, 1><<<dim3(MDIM / 64, R_TOTAL / 128), 256>>>(w1, b1, nullptr);
    // 6) out += hid @ w2^T + b2
    gemm_kernel<1024, 2><<<dim3(DH / 64, R_TOTAL / 128), 256>>>(w2, b2, out);
}